// round 5
// baseline (speedup 1.0000x reference)
#include <cuda_runtime.h>
#include <cstdint>

// Problem constants (fixed shapes per reference)
#define B_  2
#define H_  16
#define SQ_ 2048
#define SKV_ 3072
#define D_  64
#define NPT_ 1024

#define BM 64     // query rows per CTA
#define BN 64     // kv cols per tile
#define NTHREADS 256

__device__ __forceinline__ float ex2f(float x) {
    float y;
    asm("ex2.approx.ftz.f32 %0, %1;" : "=f"(y) : "f"(x));
    return y;
}

__global__ void __launch_bounds__(NTHREADS, 2)
fa_prefix_causal_kernel(const float* __restrict__ Q,
                        const float* __restrict__ K,
                        const float* __restrict__ V,
                        float* __restrict__ O)
{
    // 3 x 16KB = 49152 B static smem (fits the 48KB static limit exactly)
    __shared__ float Qs[BM * D_];     // Q tile, row-major, pre-scaled
    __shared__ float KsT[D_ * BN];    // K^T, xor-swizzled; reused as P after S GEMM
    __shared__ float Vs[BN * D_];     // V tile, row-major

    const int tid = threadIdx.x;
    const int tx = tid & 15;          // 16 column-groups
    const int ty = tid >> 4;          // 16 row-groups
    const int r0 = ty << 2;           // this thread's 4 rows
    const int c0 = tx << 2;           // this thread's 4 cols

    const int qb = blockIdx.x;        // 0..31
    const int bh = blockIdx.y;        // 0..31 (b*H+h)
    const int q0 = qb * BM;

    const float* q = Q + (size_t)bh * SQ_ * D_;
    const float* k = K + (size_t)bh * SKV_ * D_;
    const float* v = V + (size_t)bh * SKV_ * D_;
    float*       o = O + (size_t)bh * SQ_ * D_;

    // ---- load Q tile, fold in scale * log2(e) so softmax runs in exp2 domain
    const float qscale = 0.125f * 1.44269504088896340736f; // 1/sqrt(64) * log2(e)
    #pragma unroll
    for (int i = 0; i < 4; i++) {
        int e4  = tid + i * NTHREADS;         // 1024 float4s
        int row = e4 >> 4;
        int col = (e4 & 15) << 2;
        float4 t = *(const float4*)(q + (size_t)(q0 + row) * D_ + col);
        t.x *= qscale; t.y *= qscale; t.z *= qscale; t.w *= qscale;
        *(float4*)&Qs[row * D_ + col] = t;
    }

    float m[4], l[4], oacc[4][4];
    #pragma unroll
    for (int i = 0; i < 4; i++) {
        m[i] = -1e30f; l[i] = 0.f;
        #pragma unroll
        for (int j = 0; j < 4; j++) oacc[i][j] = 0.f;
    }

    // visible KV tiles: 0 .. qb+16 (mask collapses to kv <= q + 1024);
    // only the last tile needs masking, and it is exactly the diagonal c<=r.
    const int ntiles = qb + (NPT_ / BN) + 1;

    for (int t = 0; t < ntiles; t++) {
        __syncthreads();   // prior iteration done reading Ps(=KsT) and Vs

        // ---- load K tile transposed with (d&28) xor swizzle, V tile natural
        const float* kt = k + (size_t)t * BN * D_;
        const float* vt = v + (size_t)t * BN * D_;
        #pragma unroll
        for (int i = 0; i < 4; i++) {
            int e4 = tid + i * NTHREADS;
            int n  = e4 >> 4;                 // kv index in tile
            int d0 = (e4 & 15) << 2;          // head-dim base
            float4 kk4 = *(const float4*)(kt + n * D_ + d0);
            int sw = n ^ (d0 & 28);
            KsT[(d0 + 0) * BN + sw] = kk4.x;
            KsT[(d0 + 1) * BN + sw] = kk4.y;
            KsT[(d0 + 2) * BN + sw] = kk4.z;
            KsT[(d0 + 3) * BN + sw] = kk4.w;
            *(float4*)&Vs[n * D_ + d0] = *(const float4*)(vt + n * D_ + d0);
        }
        __syncthreads();

        // ---- S = (Q*scale) K^T : 4x4 register micro-tile, vectorized smem reads
        float s[4][4];
        #pragma unroll
        for (int i = 0; i < 4; i++)
            #pragma unroll
            for (int j = 0; j < 4; j++) s[i][j] = 0.f;

        #pragma unroll 4
        for (int kk4 = 0; kk4 < D_; kk4 += 4) {
            float A[4][4];
            #pragma unroll
            for (int i = 0; i < 4; i++) {
                float4 t4 = *(const float4*)&Qs[(r0 + i) * D_ + kk4];
                A[i][0] = t4.x; A[i][1] = t4.y; A[i][2] = t4.z; A[i][3] = t4.w;
            }
            #pragma unroll
            for (int u = 0; u < 4; u++) {
                int kk = kk4 + u;
                float4 b4 = *(const float4*)&KsT[kk * BN + (c0 ^ (kk & 28))];
                #pragma unroll
                for (int i = 0; i < 4; i++) {
                    s[i][0] = fmaf(A[i][u], b4.x, s[i][0]);
                    s[i][1] = fmaf(A[i][u], b4.y, s[i][1]);
                    s[i][2] = fmaf(A[i][u], b4.z, s[i][2]);
                    s[i][3] = fmaf(A[i][u], b4.w, s[i][3]);
                }
            }
        }

        // ---- diagonal mask, only on the last tile
        if (t == ntiles - 1) {
            #pragma unroll
            for (int i = 0; i < 4; i++)
                #pragma unroll
                for (int j = 0; j < 4; j++)
                    if (c0 + j > r0 + i) s[i][j] = -1e30f;
        }

        // ---- online softmax (exp2 domain); row group = 16 lanes (half-warp aligned)
        float corr[4];
        #pragma unroll
        for (int i = 0; i < 4; i++) {
            float mx = fmaxf(fmaxf(s[i][0], s[i][1]), fmaxf(s[i][2], s[i][3]));
            #pragma unroll
            for (int off = 8; off >= 1; off >>= 1)
                mx = fmaxf(mx, __shfl_xor_sync(0xffffffffu, mx, off));
            float mnew = fmaxf(m[i], mx);
            corr[i] = ex2f(m[i] - mnew);
            m[i] = mnew;
            float ps = 0.f;
            #pragma unroll
            for (int j = 0; j < 4; j++) {
                s[i][j] = ex2f(s[i][j] - mnew);
                ps += s[i][j];
            }
            #pragma unroll
            for (int off = 8; off >= 1; off >>= 1)
                ps += __shfl_xor_sync(0xffffffffu, ps, off);
            l[i] = l[i] * corr[i] + ps;
            #pragma unroll
            for (int j = 0; j < 4; j++) oacc[i][j] *= corr[i];
        }

        __syncthreads();             // all threads done reading KsT
        float* Ps = KsT;             // reuse dead K buffer for P
        #pragma unroll
        for (int i = 0; i < 4; i++)
            *(float4*)&Ps[(r0 + i) * BN + c0] =
                make_float4(s[i][0], s[i][1], s[i][2], s[i][3]);
        __syncthreads();

        // ---- O += P V : same micro-tile shape, all LDS.128
        #pragma unroll 4
        for (int kk4 = 0; kk4 < BN; kk4 += 4) {
            float P[4][4];
            #pragma unroll
            for (int i = 0; i < 4; i++) {
                float4 t4 = *(const float4*)&Ps[(r0 + i) * BN + kk4];
                P[i][0] = t4.x; P[i][1] = t4.y; P[i][2] = t4.z; P[i][3] = t4.w;
            }
            #pragma unroll
            for (int u = 0; u < 4; u++) {
                float4 v4 = *(const float4*)&Vs[(kk4 + u) * D_ + c0];
                #pragma unroll
                for (int i = 0; i < 4; i++) {
                    oacc[i][0] = fmaf(P[i][u], v4.x, oacc[i][0]);
                    oacc[i][1] = fmaf(P[i][u], v4.y, oacc[i][1]);
                    oacc[i][2] = fmaf(P[i][u], v4.z, oacc[i][2]);
                    oacc[i][3] = fmaf(P[i][u], v4.w, oacc[i][3]);
                }
            }
        }
    }

    // ---- epilogue: normalize and store
    #pragma unroll
    for (int i = 0; i < 4; i++) {
        float inv = 1.0f / l[i];
        float4 r;
        r.x = oacc[i][0] * inv;
        r.y = oacc[i][1] * inv;
        r.z = oacc[i][2] * inv;
        r.w = oacc[i][3] * inv;
        *(float4*)(o + (size_t)(q0 + r0 + i) * D_ + c0) = r;
    }
}

extern "C" void kernel_launch(void* const* d_in, const int* in_sizes, int n_in,
                              void* d_out, int out_size) {
    const float* q = (const float*)d_in[0];
    const float* k = (const float*)d_in[1];
    const float* v = (const float*)d_in[2];
    // d_in[3] = num_pt (fixed at 1024 per the problem spec; folded into tiling)
    float* out = (float*)d_out;

    dim3 grid(SQ_ / BM, B_ * H_);
    fa_prefix_causal_kernel<<<grid, NTHREADS>>>(q, k, v, out);
}

// round 6
// speedup vs baseline: 2.1924x; 2.1924x over previous
#include <cuda_runtime.h>
#include <cuda_bf16.h>
#include <cstdint>

// Problem constants (fixed shapes per reference)
#define B_   2
#define H_   16
#define SQ_  2048
#define SKV_ 3072
#define D_   64
#define NPT_ 1024

#define BM 128          // query rows per CTA
#define BN 64           // kv cols per tile
#define NTHREADS 256    // 8 warps, warp w owns rows [16w, 16w+16)
#define KPAD 72         // bf16 row stride for K/V smem (conflict-free fragment loads)
#define QS 68           // float row stride for Q staging

__device__ __forceinline__ float ex2f(float x) {
    float y; asm("ex2.approx.ftz.f32 %0, %1;" : "=f"(y) : "f"(x)); return y;
}

// D += A * B   (m16n8k16, bf16 in, fp32 accumulate)
__device__ __forceinline__ void mma_bf16(float* c, const uint32_t* a, const uint32_t* b) {
    asm volatile(
        "mma.sync.aligned.m16n8k16.row.col.f32.bf16.bf16.f32 "
        "{%0,%1,%2,%3}, {%4,%5,%6,%7}, {%8,%9}, {%0,%1,%2,%3};"
        : "+f"(c[0]), "+f"(c[1]), "+f"(c[2]), "+f"(c[3])
        : "r"(a[0]), "r"(a[1]), "r"(a[2]), "r"(a[3]), "r"(b[0]), "r"(b[1]));
}

// Split fp32 pair into packed bf16x2 (hi) + packed bf16x2 (lo residual).
__device__ __forceinline__ void split_pack(float x, float y, uint32_t& hi, uint32_t& lo) {
    __nv_bfloat16 hx = __float2bfloat16(x);
    __nv_bfloat16 hy = __float2bfloat16(y);
    __nv_bfloat16 lx = __float2bfloat16(x - __bfloat162float(hx));
    __nv_bfloat16 ly = __float2bfloat16(y - __bfloat162float(hy));
    hi = (uint32_t)__bfloat16_as_ushort(hx) | ((uint32_t)__bfloat16_as_ushort(hy) << 16);
    lo = (uint32_t)__bfloat16_as_ushort(lx) | ((uint32_t)__bfloat16_as_ushort(ly) << 16);
}

__global__ void __launch_bounds__(NTHREADS, 1)
fa_prefix_causal_mma(const float* __restrict__ Q,
                     const float* __restrict__ K,
                     const float* __restrict__ V,
                     float* __restrict__ O)
{
    // 36864 B static smem: KH/KL [64][72] bf16, VH/VL (transposed) [64][72] bf16.
    // Q staging ([128][68] fp32 = 34816 B) reuses the same space before the loop.
    __shared__ __align__(16) char smem_raw[4 * 64 * KPAD * 2];
    __nv_bfloat16* KH = (__nv_bfloat16*)smem_raw;
    __nv_bfloat16* KL = KH + 64 * KPAD;
    __nv_bfloat16* VH = KL + 64 * KPAD;   // [d][kv]
    __nv_bfloat16* VL = VH + 64 * KPAD;
    float* qstage = (float*)smem_raw;     // [128][QS]

    const int tid  = threadIdx.x;
    const int lane = tid & 31;
    const int warp = tid >> 5;
    const int g    = lane >> 2;     // fragment group (row / n-col within 8)
    const int qi   = lane & 3;      // thread-in-group (k / col pairs)
    const int wrow = warp * 16;     // this warp's first query row in the tile

    const int qb = (gridDim.x - 1) - blockIdx.x;  // heavy CTAs first
    const int bh = blockIdx.y;
    const int q0 = qb * BM;

    const float* q = Q + (size_t)bh * SQ_ * D_;
    const float* k = K + (size_t)bh * SKV_ * D_;
    const float* v = V + (size_t)bh * SKV_ * D_;
    float*       o = O + (size_t)bh * SQ_ * D_;

    // ---- stage Q (fp32, scaled) into smem, then extract resident a-fragments
    const float qscale = 0.125f * 1.44269504088896340736f; // 1/sqrt(64) * log2(e)
    #pragma unroll
    for (int p = 0; p < 8; p++) {
        int e4  = tid + p * NTHREADS;           // 2048 float4s = 128x64
        int row = e4 >> 4;
        int col = (e4 & 15) << 2;
        float4 t = *(const float4*)(q + (size_t)(q0 + row) * D_ + col);
        t.x *= qscale; t.y *= qscale; t.z *= qscale; t.w *= qscale;
        *(float4*)&qstage[row * QS + col] = t;
    }
    __syncthreads();

    // Q a-fragments: [ks][reg], reg0=row g k-lo, reg1=row g+8 k-lo, reg2=row g k-hi, reg3=row g+8 k-hi
    uint32_t qh[4][4], ql[4][4];
    #pragma unroll
    for (int ks = 0; ks < 4; ks++) {
        int clo = ks * 16 + 2 * qi;
        float2 x0 = *(const float2*)&qstage[(wrow + g)     * QS + clo];
        float2 x1 = *(const float2*)&qstage[(wrow + g + 8) * QS + clo];
        float2 x2 = *(const float2*)&qstage[(wrow + g)     * QS + clo + 8];
        float2 x3 = *(const float2*)&qstage[(wrow + g + 8) * QS + clo + 8];
        split_pack(x0.x, x0.y, qh[ks][0], ql[ks][0]);
        split_pack(x1.x, x1.y, qh[ks][1], ql[ks][1]);
        split_pack(x2.x, x2.y, qh[ks][2], ql[ks][2]);
        split_pack(x3.x, x3.y, qh[ks][3], ql[ks][3]);
    }

    float m0 = -1e30f, m1 = -1e30f, l0 = 0.f, l1 = 0.f;
    float oacc[8][4];
    #pragma unroll
    for (int nt = 0; nt < 8; nt++)
        #pragma unroll
        for (int j = 0; j < 4; j++) oacc[nt][j] = 0.f;

    // visible kv: kv <= q + 1024. Tiles 0 .. 2qb+17; last two need per-element mask.
    const int ntiles = 2 * qb + 18;
    const int tmask  = 2 * qb + 16;
    const int row0g  = q0 + wrow + g;           // this thread's even row (global)

    for (int t = 0; t < ntiles; t++) {
        __syncthreads();   // previous iteration done reading smem (or Q fragments read)

        // ---- K tile: [kv][d] bf16 hi/lo, coalesced gmem reads
        const float* kt = k + (size_t)t * BN * D_;
        #pragma unroll
        for (int p = 0; p < 4; p++) {
            int e  = tid + p * NTHREADS;        // 1024 float4s = 64x64
            int kv = e >> 4;
            int d0 = (e & 15) << 2;
            float4 f = *(const float4*)(kt + kv * D_ + d0);
            uint32_t h0, lo0, h1, lo1;
            split_pack(f.x, f.y, h0, lo0);
            split_pack(f.z, f.w, h1, lo1);
            *(uint32_t*)&KH[kv * KPAD + d0]     = h0;
            *(uint32_t*)&KH[kv * KPAD + d0 + 2] = h1;
            *(uint32_t*)&KL[kv * KPAD + d0]     = lo0;
            *(uint32_t*)&KL[kv * KPAD + d0 + 2] = lo1;
        }
        // ---- V tile: transposed [d][kv] bf16 hi/lo (lane scans kv -> low-conflict STS)
        const float* vt = v + (size_t)t * BN * D_;
        {
            int kv = tid & 63;
            int dq = tid >> 6;                  // 0..3
            #pragma unroll
            for (int p = 0; p < 4; p++) {
                int d0 = (dq * 4 + p) << 2;     // 0,4,...,60
                float4 f = *(const float4*)(vt + kv * D_ + d0);
                float  fv[4] = {f.x, f.y, f.z, f.w};
                #pragma unroll
                for (int j = 0; j < 4; j++) {
                    __nv_bfloat16 h = __float2bfloat16(fv[j]);
                    __nv_bfloat16 l = __float2bfloat16(fv[j] - __bfloat162float(h));
                    VH[(d0 + j) * KPAD + kv] = h;
                    VL[(d0 + j) * KPAD + kv] = l;
                }
            }
        }
        __syncthreads();

        // ---- S = Q K^T  (3-mma bf16 split per k-step)
        float sc[8][4];
        #pragma unroll
        for (int nt = 0; nt < 8; nt++)
            #pragma unroll
            for (int j = 0; j < 4; j++) sc[nt][j] = 0.f;

        #pragma unroll
        for (int nt = 0; nt < 8; nt++) {
            const __nv_bfloat16* khr = &KH[(nt * 8 + g) * KPAD + 2 * qi];
            const __nv_bfloat16* klr = &KL[(nt * 8 + g) * KPAD + 2 * qi];
            #pragma unroll
            for (int ks = 0; ks < 4; ks++) {
                uint32_t bh[2], bl[2];
                bh[0] = *(const uint32_t*)&khr[ks * 16];
                bh[1] = *(const uint32_t*)&khr[ks * 16 + 8];
                bl[0] = *(const uint32_t*)&klr[ks * 16];
                bl[1] = *(const uint32_t*)&klr[ks * 16 + 8];
                mma_bf16(sc[nt], qh[ks], bh);
                mma_bf16(sc[nt], ql[ks], bh);
                mma_bf16(sc[nt], qh[ks], bl);
            }
        }

        // ---- mask (last two tiles only): visible iff kv_global <= q_global + NPT
        if (t >= tmask) {
            int colbase = t * 64;
            #pragma unroll
            for (int nt = 0; nt < 8; nt++) {
                int c = colbase + nt * 8 + 2 * qi;
                if (c     > row0g + NPT_)     sc[nt][0] = -1e30f;
                if (c + 1 > row0g + NPT_)     sc[nt][1] = -1e30f;
                if (c     > row0g + 8 + NPT_) sc[nt][2] = -1e30f;
                if (c + 1 > row0g + 8 + NPT_) sc[nt][3] = -1e30f;
            }
        }

        // ---- online softmax (exp2 domain); row reduce over the 4-lane quad
        float mx0 = -1e30f, mx1 = -1e30f;
        #pragma unroll
        for (int nt = 0; nt < 8; nt++) {
            mx0 = fmaxf(mx0, fmaxf(sc[nt][0], sc[nt][1]));
            mx1 = fmaxf(mx1, fmaxf(sc[nt][2], sc[nt][3]));
        }
        #pragma unroll
        for (int off = 1; off <= 2; off <<= 1) {
            mx0 = fmaxf(mx0, __shfl_xor_sync(0xffffffffu, mx0, off));
            mx1 = fmaxf(mx1, __shfl_xor_sync(0xffffffffu, mx1, off));
        }
        float mn0 = fmaxf(m0, mx0), mn1 = fmaxf(m1, mx1);
        float cr0 = ex2f(m0 - mn0), cr1 = ex2f(m1 - mn1);
        m0 = mn0; m1 = mn1;

        float ps0 = 0.f, ps1 = 0.f;
        #pragma unroll
        for (int nt = 0; nt < 8; nt++) {
            sc[nt][0] = ex2f(sc[nt][0] - mn0);
            sc[nt][1] = ex2f(sc[nt][1] - mn0);
            sc[nt][2] = ex2f(sc[nt][2] - mn1);
            sc[nt][3] = ex2f(sc[nt][3] - mn1);
            ps0 += sc[nt][0] + sc[nt][1];
            ps1 += sc[nt][2] + sc[nt][3];
        }
        #pragma unroll
        for (int off = 1; off <= 2; off <<= 1) {
            ps0 += __shfl_xor_sync(0xffffffffu, ps0, off);
            ps1 += __shfl_xor_sync(0xffffffffu, ps1, off);
        }
        l0 = l0 * cr0 + ps0;
        l1 = l1 * cr1 + ps1;
        #pragma unroll
        for (int nt = 0; nt < 8; nt++) {
            oacc[nt][0] *= cr0; oacc[nt][1] *= cr0;
            oacc[nt][2] *= cr1; oacc[nt][3] *= cr1;
        }

        // ---- O += P V : S c-fragments repack directly into PV a-fragments (no smem)
        #pragma unroll
        for (int ks = 0; ks < 4; ks++) {
            uint32_t pah[4], pal[4];
            split_pack(sc[2*ks][0],   sc[2*ks][1],   pah[0], pal[0]);
            split_pack(sc[2*ks][2],   sc[2*ks][3],   pah[1], pal[1]);
            split_pack(sc[2*ks+1][0], sc[2*ks+1][1], pah[2], pal[2]);
            split_pack(sc[2*ks+1][2], sc[2*ks+1][3], pah[3], pal[3]);
            #pragma unroll
            for (int nt = 0; nt < 8; nt++) {
                const __nv_bfloat16* vhr = &VH[(nt * 8 + g) * KPAD + ks * 16 + 2 * qi];
                const __nv_bfloat16* vlr = &VL[(nt * 8 + g) * KPAD + ks * 16 + 2 * qi];
                uint32_t vh[2], vl[2];
                vh[0] = *(const uint32_t*)&vhr[0];
                vh[1] = *(const uint32_t*)&vhr[8];
                vl[0] = *(const uint32_t*)&vlr[0];
                vl[1] = *(const uint32_t*)&vlr[8];
                mma_bf16(oacc[nt], pah, vh);
                mma_bf16(oacc[nt], pal, vh);
                mma_bf16(oacc[nt], pah, vl);
            }
        }
    }

    // ---- epilogue: normalize and store (float2 per n-tile per row half)
    float inv0 = 1.0f / l0, inv1 = 1.0f / l1;
    #pragma unroll
    for (int nt = 0; nt < 8; nt++) {
        int col = nt * 8 + 2 * qi;
        *(float2*)(o + (size_t)(row0g)     * D_ + col) =
            make_float2(oacc[nt][0] * inv0, oacc[nt][1] * inv0);
        *(float2*)(o + (size_t)(row0g + 8) * D_ + col) =
            make_float2(oacc[nt][2] * inv1, oacc[nt][3] * inv1);
    }
}

extern "C" void kernel_launch(void* const* d_in, const int* in_sizes, int n_in,
                              void* d_out, int out_size) {
    const float* q = (const float*)d_in[0];
    const float* k = (const float*)d_in[1];
    const float* v = (const float*)d_in[2];
    // d_in[3] = num_pt (fixed at 1024 per the problem spec; folded into tiling)
    float* out = (float*)d_out;

    dim3 grid(SQ_ / BM, B_ * H_);
    fa_prefix_causal_mma<<<grid, NTHREADS>>>(q, k, v, out);
}

// round 7
// speedup vs baseline: 3.3452x; 1.5258x over previous
#include <cuda_runtime.h>
#include <cuda_bf16.h>
#include <cstdint>

// Problem constants (fixed shapes per reference)
#define B_   2
#define H_   16
#define SQ_  2048
#define SKV_ 3072
#define D_   64
#define NPT_ 1024

#define BM 128          // query rows per CTA
#define BN 64           // kv cols per tile
#define NTHREADS 256    // 8 warps, warp w owns rows [16w, 16w+16)
#define KPAD 72         // bf16 row stride for K/V smem (conflict-free ldmatrix rows)
#define QS 68           // float row stride for Q staging

#define ARR_B   (64 * KPAD * 2)          // bytes per bf16 [64][72] array = 9216
#define BUF_B   (4 * ARR_B)              // KH,KL,VH,VL per buffer = 36864
#define SMEM_B  (2 * BUF_B)              // double buffered = 73728

__device__ __forceinline__ float ex2f(float x) {
    float y; asm("ex2.approx.ftz.f32 %0, %1;" : "=f"(y) : "f"(x)); return y;
}

// D += A * B   (m16n8k16, bf16 in, fp32 accumulate)
__device__ __forceinline__ void mma_bf16(float* c, const uint32_t* a, const uint32_t* b) {
    asm volatile(
        "mma.sync.aligned.m16n8k16.row.col.f32.bf16.bf16.f32 "
        "{%0,%1,%2,%3}, {%4,%5,%6,%7}, {%8,%9}, {%0,%1,%2,%3};"
        : "+f"(c[0]), "+f"(c[1]), "+f"(c[2]), "+f"(c[3])
        : "r"(a[0]), "r"(a[1]), "r"(a[2]), "r"(a[3]), "r"(b[0]), "r"(b[1]));
}

__device__ __forceinline__ void ldsm_x4(uint32_t* r, uint32_t addr) {
    asm volatile("ldmatrix.sync.aligned.m8n8.x4.shared.b16 {%0,%1,%2,%3}, [%4];"
        : "=r"(r[0]), "=r"(r[1]), "=r"(r[2]), "=r"(r[3]) : "r"(addr));
}
__device__ __forceinline__ void ldsm_x4_t(uint32_t* r, uint32_t addr) {
    asm volatile("ldmatrix.sync.aligned.m8n8.x4.trans.shared.b16 {%0,%1,%2,%3}, [%4];"
        : "=r"(r[0]), "=r"(r[1]), "=r"(r[2]), "=r"(r[3]) : "r"(addr));
}

// Split fp32 pair into packed bf16x2 (hi) + packed bf16x2 (lo residual).
__device__ __forceinline__ void split_pack(float x, float y, uint32_t& hi, uint32_t& lo) {
    __nv_bfloat162 h = __floats2bfloat162_rn(x, y);
    float hx = __bfloat162float(h.x), hy = __bfloat162float(h.y);
    __nv_bfloat162 l = __floats2bfloat162_rn(x - hx, y - hy);
    hi = *(uint32_t*)&h; lo = *(uint32_t*)&l;
}

__global__ void __launch_bounds__(NTHREADS, 1)
fa_prefix_causal_mma2(const float* __restrict__ Q,
                      const float* __restrict__ K,
                      const float* __restrict__ V,
                      float* __restrict__ O)
{
    extern __shared__ __align__(16) char dsmem[];
    // buffer b: KH | KL | VH | VL, each [64][KPAD] bf16, all stored [kv][d]
    float* qstage = (float*)dsmem;   // [128][QS] fp32, lives in buffer 0 pre-loop
    const uint32_t smem_u = (uint32_t)__cvta_generic_to_shared(dsmem);

    const int tid  = threadIdx.x;
    const int lane = tid & 31;
    const int warp = tid >> 5;
    const int g    = lane >> 2;
    const int qi   = lane & 3;
    const int wrow = warp * 16;

    // ldmatrix lane address components
    const int ti    = lane >> 3;          // tile index within x4
    const int rr    = lane & 7;           // row within tile
    const int ks_in = ti >> 1;            // ks offset within kp-pair
    const int off8  = (ti & 1) * 8;       // k-offset 0/8 within 16-chunk
    // S (non-trans): rows = kv (nt*8 + rr), col base = d = kp*32 + ks_in*16 + off8
    const uint32_t s_lane = (uint32_t)(rr * KPAD + ks_in * 16 + off8) * 2;
    // PV (trans): rows = kv (kp*32 + ks_in*16 + off8 + rr), col base = d = nt*8
    const uint32_t p_lane = (uint32_t)((ks_in * 16 + off8 + rr) * KPAD) * 2;

    const int qb = (gridDim.x - 1) - blockIdx.x;   // heavy CTAs first
    const int bh = blockIdx.y;
    const int q0 = qb * BM;

    const float* q = Q + (size_t)bh * SQ_ * D_;
    const float* k = K + (size_t)bh * SKV_ * D_;
    const float* v = V + (size_t)bh * SKV_ * D_;
    float*       o = O + (size_t)bh * SQ_ * D_;

    // ---- stage Q (fp32, scaled) into smem buffer 0
    const float qscale = 0.125f * 1.44269504088896340736f; // 1/sqrt(64) * log2(e)
    #pragma unroll
    for (int p = 0; p < 8; p++) {
        int e4  = tid + p * NTHREADS;
        int row = e4 >> 4;
        int col = (e4 & 15) << 2;
        float4 t = *(const float4*)(q + (size_t)(q0 + row) * D_ + col);
        t.x *= qscale; t.y *= qscale; t.z *= qscale; t.w *= qscale;
        *(float4*)&qstage[row * QS + col] = t;
    }
    __syncthreads();

    // ---- prefetch tile 0 K/V while extracting Q fragments
    float4 pre[8];
    {
        const float4* kt4 = (const float4*)k;
        const float4* vt4 = (const float4*)v;
        #pragma unroll
        for (int p = 0; p < 4; p++) {
            pre[p]     = kt4[tid + p * NTHREADS];
            pre[4 + p] = vt4[tid + p * NTHREADS];
        }
    }

    // Q a-fragments: reg0=row g k-lo, reg1=row g+8 k-lo, reg2=row g k-hi, reg3=row g+8 k-hi
    uint32_t qh[4][4], ql[4][4];
    #pragma unroll
    for (int ks = 0; ks < 4; ks++) {
        int clo = ks * 16 + 2 * qi;
        float2 x0 = *(const float2*)&qstage[(wrow + g)     * QS + clo];
        float2 x1 = *(const float2*)&qstage[(wrow + g + 8) * QS + clo];
        float2 x2 = *(const float2*)&qstage[(wrow + g)     * QS + clo + 8];
        float2 x3 = *(const float2*)&qstage[(wrow + g + 8) * QS + clo + 8];
        split_pack(x0.x, x0.y, qh[ks][0], ql[ks][0]);
        split_pack(x1.x, x1.y, qh[ks][1], ql[ks][1]);
        split_pack(x2.x, x2.y, qh[ks][2], ql[ks][2]);
        split_pack(x3.x, x3.y, qh[ks][3], ql[ks][3]);
    }
    __syncthreads();   // everyone done reading qstage; buffer 0 free for tile 0

    float m0 = -1e30f, m1 = -1e30f, l0 = 0.f, l1 = 0.f;
    float oacc[8][4];
    #pragma unroll
    for (int nt = 0; nt < 8; nt++)
        #pragma unroll
        for (int j = 0; j < 4; j++) oacc[nt][j] = 0.f;

    // visible kv: kv <= q + 1024. Tiles 0 .. 2qb+17; last two need per-element mask.
    const int ntiles = 2 * qb + 18;
    const int tmask  = 2 * qb + 16;
    const int row0g  = q0 + wrow + g;

    // STS lane mapping (same for K and V, both [kv][d])
    const int skv = tid >> 4;            // base kv row for p-group
    const int sd0 = (tid & 15) << 2;     // d base

    for (int t = 0; t < ntiles; t++) {
        const uint32_t bufu = smem_u + (uint32_t)(t & 1) * BUF_B;
        char* bufc = dsmem + (size_t)(t & 1) * BUF_B;
        __nv_bfloat16* KH = (__nv_bfloat16*)(bufc);
        __nv_bfloat16* KL = (__nv_bfloat16*)(bufc + ARR_B);
        __nv_bfloat16* VH = (__nv_bfloat16*)(bufc + 2 * ARR_B);
        __nv_bfloat16* VL = (__nv_bfloat16*)(bufc + 3 * ARR_B);

        // ---- convert + store prefetched tile t (K and V identical path)
        #pragma unroll
        for (int p = 0; p < 8; p++) {
            __nv_bfloat16* H = (p < 4) ? KH : VH;
            __nv_bfloat16* L = (p < 4) ? KL : VL;
            int kv = skv + (p & 3) * 16;
            float4 f = pre[p];
            uint32_t h0, lo0, h1, lo1;
            split_pack(f.x, f.y, h0, lo0);
            split_pack(f.z, f.w, h1, lo1);
            *(uint2*)&H[kv * KPAD + sd0] = make_uint2(h0, h1);
            *(uint2*)&L[kv * KPAD + sd0] = make_uint2(lo0, lo1);
        }
        __syncthreads();   // single barrier per tile (2-buffer hazard-free)

        // ---- prefetch tile t+1 (clamped; overlaps with compute below)
        {
            int tn = min(t + 1, ntiles - 1);
            const float4* kt4 = (const float4*)(k + (size_t)tn * BN * D_);
            const float4* vt4 = (const float4*)(v + (size_t)tn * BN * D_);
            #pragma unroll
            for (int p = 0; p < 4; p++) {
                pre[p]     = kt4[tid + p * NTHREADS];
                pre[4 + p] = vt4[tid + p * NTHREADS];
            }
        }

        // ---- S = Q K^T  (3-mma bf16 split; b-frags via ldmatrix.x4)
        float sc[8][4];
        #pragma unroll
        for (int nt = 0; nt < 8; nt++)
            #pragma unroll
            for (int j = 0; j < 4; j++) sc[nt][j] = 0.f;

        #pragma unroll
        for (int nt = 0; nt < 8; nt++) {
            uint32_t rowb = bufu + s_lane + (uint32_t)nt * (8 * KPAD * 2);
            #pragma unroll
            for (int kp = 0; kp < 2; kp++) {
                uint32_t bh4[4], bl4[4];
                ldsm_x4(bh4, rowb + kp * 64);
                ldsm_x4(bl4, rowb + ARR_B + kp * 64);
                mma_bf16(sc[nt], qh[2*kp],   bh4 + 0);
                mma_bf16(sc[nt], ql[2*kp],   bh4 + 0);
                mma_bf16(sc[nt], qh[2*kp],   bl4 + 0);
                mma_bf16(sc[nt], qh[2*kp+1], bh4 + 2);
                mma_bf16(sc[nt], ql[2*kp+1], bh4 + 2);
                mma_bf16(sc[nt], qh[2*kp+1], bl4 + 2);
            }
        }

        // ---- mask (last two tiles only): visible iff kv_global <= q_global + NPT
        if (t >= tmask) {
            int colbase = t * 64;
            #pragma unroll
            for (int nt = 0; nt < 8; nt++) {
                int c = colbase + nt * 8 + 2 * qi;
                if (c     > row0g + NPT_)     sc[nt][0] = -1e30f;
                if (c + 1 > row0g + NPT_)     sc[nt][1] = -1e30f;
                if (c     > row0g + 8 + NPT_) sc[nt][2] = -1e30f;
                if (c + 1 > row0g + 8 + NPT_) sc[nt][3] = -1e30f;
            }
        }

        // ---- online softmax (exp2 domain); row reduce over the 4-lane quad
        float mx0 = -1e30f, mx1 = -1e30f;
        #pragma unroll
        for (int nt = 0; nt < 8; nt++) {
            mx0 = fmaxf(mx0, fmaxf(sc[nt][0], sc[nt][1]));
            mx1 = fmaxf(mx1, fmaxf(sc[nt][2], sc[nt][3]));
        }
        #pragma unroll
        for (int off = 1; off <= 2; off <<= 1) {
            mx0 = fmaxf(mx0, __shfl_xor_sync(0xffffffffu, mx0, off));
            mx1 = fmaxf(mx1, __shfl_xor_sync(0xffffffffu, mx1, off));
        }
        float mn0 = fmaxf(m0, mx0), mn1 = fmaxf(m1, mx1);
        float cr0 = ex2f(m0 - mn0), cr1 = ex2f(m1 - mn1);
        m0 = mn0; m1 = mn1;

        float ps0 = 0.f, ps1 = 0.f;
        #pragma unroll
        for (int nt = 0; nt < 8; nt++) {
            sc[nt][0] = ex2f(sc[nt][0] - mn0);
            sc[nt][1] = ex2f(sc[nt][1] - mn0);
            sc[nt][2] = ex2f(sc[nt][2] - mn1);
            sc[nt][3] = ex2f(sc[nt][3] - mn1);
            ps0 += sc[nt][0] + sc[nt][1];
            ps1 += sc[nt][2] + sc[nt][3];
        }
        #pragma unroll
        for (int off = 1; off <= 2; off <<= 1) {
            ps0 += __shfl_xor_sync(0xffffffffu, ps0, off);
            ps1 += __shfl_xor_sync(0xffffffffu, ps1, off);
        }
        l0 = l0 * cr0 + ps0;
        l1 = l1 * cr1 + ps1;
        #pragma unroll
        for (int nt = 0; nt < 8; nt++) {
            oacc[nt][0] *= cr0; oacc[nt][1] *= cr0;
            oacc[nt][2] *= cr1; oacc[nt][3] *= cr1;
        }

        // ---- O += P V : repack S c-frags into PV a-frags; V b-frags via ldmatrix.trans
        #pragma unroll
        for (int kp = 0; kp < 2; kp++) {
            uint32_t pah[2][4], pal[2][4];
            #pragma unroll
            for (int kk = 0; kk < 2; kk++) {
                int ks = 2 * kp + kk;
                split_pack(sc[2*ks][0],   sc[2*ks][1],   pah[kk][0], pal[kk][0]);
                split_pack(sc[2*ks][2],   sc[2*ks][3],   pah[kk][1], pal[kk][1]);
                split_pack(sc[2*ks+1][0], sc[2*ks+1][1], pah[kk][2], pal[kk][2]);
                split_pack(sc[2*ks+1][2], sc[2*ks+1][3], pah[kk][3], pal[kk][3]);
            }
            uint32_t vrow = bufu + 2 * ARR_B + p_lane + (uint32_t)kp * (32 * KPAD * 2);
            #pragma unroll
            for (int nt = 0; nt < 8; nt++) {
                uint32_t vh4[4], vl4[4];
                ldsm_x4_t(vh4, vrow + nt * 16);
                ldsm_x4_t(vl4, vrow + ARR_B + nt * 16);
                mma_bf16(oacc[nt], pah[0], vh4 + 0);
                mma_bf16(oacc[nt], pal[0], vh4 + 0);
                mma_bf16(oacc[nt], pah[0], vl4 + 0);
                mma_bf16(oacc[nt], pah[1], vh4 + 2);
                mma_bf16(oacc[nt], pal[1], vh4 + 2);
                mma_bf16(oacc[nt], pah[1], vl4 + 2);
            }
        }
    }

    // ---- epilogue: normalize and store
    float inv0 = 1.0f / l0, inv1 = 1.0f / l1;
    #pragma unroll
    for (int nt = 0; nt < 8; nt++) {
        int col = nt * 8 + 2 * qi;
        *(float2*)(o + (size_t)(row0g)     * D_ + col) =
            make_float2(oacc[nt][0] * inv0, oacc[nt][1] * inv0);
        *(float2*)(o + (size_t)(row0g + 8) * D_ + col) =
            make_float2(oacc[nt][2] * inv1, oacc[nt][3] * inv1);
    }
}

extern "C" void kernel_launch(void* const* d_in, const int* in_sizes, int n_in,
                              void* d_out, int out_size) {
    const float* q = (const float*)d_in[0];
    const float* k = (const float*)d_in[1];
    const float* v = (const float*)d_in[2];
    // d_in[3] = num_pt (fixed at 1024 per the problem spec; folded into tiling)
    float* out = (float*)d_out;

    cudaFuncSetAttribute(fa_prefix_causal_mma2,
                         cudaFuncAttributeMaxDynamicSharedMemorySize, SMEM_B);

    dim3 grid(SQ_ / BM, B_ * H_);
    fa_prefix_causal_mma2<<<grid, NTHREADS, SMEM_B>>>(q, k, v, out);
}